// round 13
// baseline (speedup 1.0000x reference)
#include <cuda_runtime.h>
#include <math.h>

#define N_NODES 20000
#define N_EDGES 160000
#define OUT_PER_NODE 36

typedef unsigned long long u64;

__device__ __forceinline__ u64 pack2(float a, float b) {
    u64 r; asm("mov.b64 %0, {%1,%2};" : "=l"(r) : "f"(a), "f"(b)); return r;
}
__device__ __forceinline__ void unpack2(u64 v, float& a, float& b) {
    asm("mov.b64 {%0,%1}, %2;" : "=f"(a), "=f"(b) : "l"(v));
}
__device__ __forceinline__ void ffma2(u64& d, u64 a, u64 b) {
    asm("fma.rn.f32x2 %0, %1, %2, %0;" : "+l"(d) : "l"(a), "l"(b));
}
__device__ __forceinline__ float silu_f(float x) {
    return __fdividef(x, 1.0f + __expf(-x));
}

// ---------------- scratch ----------------
__device__ float d_Ai[N_NODES * 8];
__device__ u64   d_Aip[N_NODES * 4];
__device__ float d_g3[N_EDGES * 64];        // [slot][c]  (CSR-slot ordered)
__device__ float d_sh[N_EDGES * 8];         // [slot][..]
__device__ float d_Ml[3 * 512 * 32];        // [l][cu][v*4+w]
__device__ int   d_deg[N_NODES];
__device__ int   d_rowptr[N_NODES + 1];
__device__ int   d_fill[N_NODES];
__device__ int   d_csr[N_EDGES];
__device__ int   d_srcs[N_EDGES];           // src node per CSR slot

__global__ void k_zero() {
    int i = blockIdx.x * blockDim.x + threadIdx.x;
    if (i < N_NODES) d_deg[i] = 0;
}

// ---------------- kernel 2: node MLP + M permute + degree count ----------------
#define NODE_BLOCKS 79
#define PERM_BLOCKS 192
__global__ __launch_bounds__(256) void k_prepcount(
    const float* __restrict__ emb_table,
    const float* __restrict__ w1, const float* __restrict__ b1,
    const float* __restrict__ w2, const float* __restrict__ b2,
    const float* __restrict__ w3, const float* __restrict__ b3,
    const int* __restrict__ A,
    const float* __restrict__ fc_w4,
    const int* __restrict__ edge_dst)
{
    int tid = threadIdx.x;
    int bx = blockIdx.x;
    if (bx >= NODE_BLOCKS + PERM_BLOCKS) {
        int e = (bx - NODE_BLOCKS - PERM_BLOCKS) * 256 + tid;
        if (e < N_EDGES) atomicAdd(&d_deg[edge_dst[e]], 1);
        return;
    }
    if (bx >= NODE_BLOCKS) {
        int idx = (bx - NODE_BLOCKS) * 256 + tid;
        int c = idx / 768;
        int rem = idx - c * 768;
        int l = rem / 256;
        int rem2 = rem - l * 256;
        int u = rem2 / 32;
        int vw = rem2 - u * 32;
        d_Ml[l * (512 * 32) + (c * 8 + u) * 32 + vw] = fc_w4[idx];
        return;
    }

    __shared__ __align__(16) float s_w1[16 * 64];
    __shared__ __align__(16) float s_w2[64 * 32];
    __shared__ __align__(16) float s_w3[32 * 8];
    __shared__ float s_b1[64];
    __shared__ float s_b2[32];
    __shared__ float s_b3[8];
    for (int i = tid; i < 16 * 64; i += 256) s_w1[i] = w1[i];
    for (int i = tid; i < 64 * 32; i += 256) s_w2[i] = w2[i];
    for (int i = tid; i < 32 * 8;  i += 256) s_w3[i] = w3[i];
    if (tid < 64) s_b1[tid] = b1[tid];
    if (tid < 32) s_b2[tid] = b2[tid];
    if (tid < 8)  s_b3[tid] = b3[tid];
    __syncthreads();

    int n = bx * 256 + tid;
    if (n >= N_NODES) return;

    int a = A[n];
    float e[16];
    #pragma unroll
    for (int i = 0; i < 16; i++) e[i] = emb_table[a * 16 + i];

    float h1[64];
    #pragma unroll
    for (int j = 0; j < 64; j++) h1[j] = s_b1[j];
    #pragma unroll
    for (int i = 0; i < 16; i++) {
        float ei = e[i];
        #pragma unroll
        for (int j = 0; j < 64; j++) h1[j] += ei * s_w1[i * 64 + j];
    }
    #pragma unroll
    for (int j = 0; j < 64; j++) h1[j] = silu_f(h1[j]);

    float h2[32];
    #pragma unroll
    for (int j = 0; j < 32; j++) h2[j] = s_b2[j];
    #pragma unroll
    for (int i = 0; i < 64; i++) {
        float hi = h1[i];
        #pragma unroll
        for (int j = 0; j < 32; j++) h2[j] += hi * s_w2[i * 32 + j];
    }
    #pragma unroll
    for (int j = 0; j < 32; j++) h2[j] = silu_f(h2[j]);

    float ai[8];
    #pragma unroll
    for (int j = 0; j < 8; j++) ai[j] = s_b3[j];
    #pragma unroll
    for (int i = 0; i < 32; i++) {
        float hi = h2[i];
        #pragma unroll
        for (int j = 0; j < 8; j++) ai[j] += hi * s_w3[i * 8 + j];
    }
    #pragma unroll
    for (int j = 0; j < 8; j++) d_Ai[n * 8 + j] = ai[j];
    #pragma unroll
    for (int j = 0; j < 4; j++) d_Aip[n * 4 + j] = pack2(ai[2 * j], ai[2 * j + 1]);
}

// ---------------- kernel 3: single-block prefix scan ----------------
__global__ __launch_bounds__(1024) void k_scan() {
    __shared__ int sbuf[1024];
    int tid = threadIdx.x;
    int carry = 0;
    if (tid == 0) d_rowptr[0] = 0;
    for (int base = 0; base < N_NODES; base += 1024) {
        int i = base + tid;
        int v = (i < N_NODES) ? d_deg[i] : 0;
        sbuf[tid] = v;
        __syncthreads();
        for (int off = 1; off < 1024; off <<= 1) {
            int t = (tid >= off) ? sbuf[tid - off] : 0;
            __syncthreads();
            sbuf[tid] += t;
            __syncthreads();
        }
        if (i < N_NODES) d_rowptr[i + 1] = carry + sbuf[tid];
        int tot = sbuf[1023];
        __syncthreads();
        carry += tot;
    }
    __syncthreads();
    for (int i = tid; i < N_NODES; i += 1024) d_fill[i] = d_rowptr[i];
}

// ---------------- kernel 4: scatter edges into CSR (+src gather) ----------------
__global__ void k_scatter(const int* __restrict__ edge_dst,
                          const int* __restrict__ edge_src) {
    int e = blockIdx.x * 256 + threadIdx.x;
    if (e < N_EDGES) {
        int p = atomicAdd(&d_fill[edge_dst[e]], 1);
        d_csr[p] = e;
        d_srcs[p] = edge_src[e];
    }
}

// ---------------- geometry helper ----------------
__device__ __forceinline__ void edge_geom(
    const float* __restrict__ pos, const int* __restrict__ batch,
    const float* __restrict__ shifts, const float* __restrict__ cell,
    int e, int s, int d, float& ex, float& ey, float& ez, float& r)
{
    float sx = shifts[e * 3 + 0], sy = shifts[e * 3 + 1], sz = shifts[e * 3 + 2];
    int b = batch[s];
    const float* C = cell + b * 9;
    float shx = sx * C[0] + sy * C[3] + sz * C[6];
    float shy = sx * C[1] + sy * C[4] + sz * C[7];
    float shz = sx * C[2] + sy * C[5] + sz * C[8];
    ex = pos[d * 3 + 0] - pos[s * 3 + 0] + shx;
    ey = pos[d * 3 + 1] - pos[s * 3 + 1] + shy;
    ez = pos[d * 3 + 2] - pos[s * 3 + 2] + shz;
    r = sqrtf(ex * ex + ey * ey + ez * ez);
}

// ---------------- tiled MLP layer: thread tile 4 edges x 8 outputs ----------------
// inb: [DEPTH][128], outb: [64][128], w: [DEPTH][64]; eg in [0,32), og in [0,8)
template<int DEPTH>
__device__ __forceinline__ void gemm_layer(
    const float* __restrict__ inb, float* __restrict__ outb,
    const float* __restrict__ w, float scale, int eg, int og)
{
    const int e0 = eg * 4;
    u64 acc[8][2];
    #pragma unroll
    for (int o = 0; o < 8; o++) { acc[o][0] = 0ULL; acc[o][1] = 0ULL; }

    #pragma unroll 4
    for (int i = 0; i < DEPTH; i++) {
        ulonglong2 a = *(const ulonglong2*)&inb[i * 128 + e0];
        float4 w0 = *(const float4*)&w[i * 64 + og * 8];
        float4 w1 = *(const float4*)&w[i * 64 + og * 8 + 4];
        float wv[8] = {w0.x, w0.y, w0.z, w0.w, w1.x, w1.y, w1.z, w1.w};
        #pragma unroll
        for (int o = 0; o < 8; o++) {
            u64 wd = pack2(wv[o], wv[o]);
            ffma2(acc[o][0], wd, a.x);
            ffma2(acc[o][1], wd, a.y);
        }
    }
    #pragma unroll
    for (int o = 0; o < 8; o++) {
        float f[4];
        unpack2(acc[o][0], f[0], f[1]);
        unpack2(acc[o][1], f[2], f[3]);
        #pragma unroll
        for (int k = 0; k < 4; k++) f[k] = silu_f(f[k] * scale);
        *(float4*)&outb[(og * 8 + o) * 128 + e0] = make_float4(f[0], f[1], f[2], f[3]);
    }
}

// ---------------- kernel 5: radial chain, slot-ordered, 256 threads ----------------
#define R_W1 0
#define R_W2 1024
#define R_W3 5120
#define R_BA 9216
#define R_BB 17408
#define R_SMEM_BYTES (25600 * 4)

__global__ __launch_bounds__(256) void k_radial(
    const float* __restrict__ pos, const int* __restrict__ batch,
    const float* __restrict__ shifts, const float* __restrict__ cell,
    const int* __restrict__ dst_arr,
    const float* __restrict__ fw1, const float* __restrict__ fw2,
    const float* __restrict__ fw3)
{
    extern __shared__ __align__(16) float sm[];
    int tid = threadIdx.x;
    for (int i = tid; i < 1024; i += 256) sm[R_W1 + i] = fw1[i];
    for (int i = tid; i < 4096; i += 256) sm[R_W2 + i] = fw2[i];
    for (int i = tid; i < 4096; i += 256) sm[R_W3 + i] = fw3[i];

    const int slot0 = blockIdx.x * 128;
    // P0: first 128 threads do geometry + sh + rb for one slot each
    if (tid < 128) {
        int slot = slot0 + tid;
        int e = d_csr[slot];
        int s = d_srcs[slot];
        int d = dst_arr[e];
        float ex, ey, ez, r;
        edge_geom(pos, batch, shifts, cell, e, s, d, ex, ey, ez, r);

        float inv_r = __fdividef(1.0f, fmaxf(r, 1e-9f));
        float x = ex * inv_r, y = ey * inv_r, z = ez * inv_r;
        const float s3 = 1.7320508075688772f;
        const float s15 = 3.872983346207417f;
        const float s5 = 2.23606797749979f;
        *(float4*)&d_sh[slot * 8 + 0] = make_float4(s3 * y, s3 * z, s3 * x, s15 * x * y);
        *(float4*)&d_sh[slot * 8 + 4] = make_float4(s15 * y * z,
                                                    0.5f * s5 * (3.0f * z * z - 1.0f),
                                                    s15 * x * z,
                                                    0.5f * s15 * (x * x - y * y));
        const float step = 5.0f / 17.0f;
        const float inv_step = 17.0f / 5.0f;
        const float rb_scale = 4.0f / 1.12f;
        #pragma unroll
        for (int j = 0; j < 16; j++) {
            float c = step * (float)(j + 1);
            float t = (r - c) * inv_step;
            sm[R_BA + j * 128 + tid] = __expf(-t * t) * rb_scale;
        }
    }
    __syncthreads();

    const int eg = tid & 31, og = tid >> 5;

    gemm_layer<16>(sm + R_BA, sm + R_BB, sm + R_W1, 0.25f, eg, og);
    __syncthreads();
    gemm_layer<64>(sm + R_BB, sm + R_BA, sm + R_W2, 0.125f, eg, og);
    __syncthreads();
    gemm_layer<64>(sm + R_BA, sm + R_BB, sm + R_W3, 0.125f, eg, og);
    __syncthreads();

    // transpose out: bufB [c][edge] -> d_g3[slot][c]; thread: edge = tid&127, c-half
    {
        int le = tid & 127;
        int ch = (tid >> 7) * 32;
        int slot = slot0 + le;
        #pragma unroll
        for (int k = 0; k < 8; k++) {
            float4 v = make_float4(sm[R_BB + (ch + k * 4 + 0) * 128 + le],
                                   sm[R_BB + (ch + k * 4 + 1) * 128 + le],
                                   sm[R_BB + (ch + k * 4 + 2) * 128 + le],
                                   sm[R_BB + (ch + k * 4 + 3) * 128 + le]);
            *(float4*)&d_g3[slot * 64 + ch + k * 4] = v;
        }
    }
}

// ---------------- kernel 6: factorized contraction, warp-per-node, per-l ----------------
template<int L>
__global__ __launch_bounds__(256, (L == 0) ? 3 : 2) void k_main(
    float* __restrict__ out)
{
    constexpr int K   = (L == 0) ? 1 : (L == 1) ? 3 : 5;
    constexpr int OFF = (L == 0) ? 0 : (L == 1) ? 4 : 16;
    extern __shared__ float sM[];

    for (int idx = threadIdx.x; idx < 16384; idx += 256) {
        int cu = idx >> 5, vw = idx & 31;
        int v = vw >> 2, w = vw & 3;
        int pv = v ^ ((cu >> 4) & 7);
        sM[(cu << 5) + (pv << 2) + w] = d_Ml[L * 16384 + idx];
    }
    __syncthreads();

    const int wid = threadIdx.x >> 5;
    const int lane = threadIdx.x & 31;
    const u64 ONE2 = pack2(1.0f, 1.0f);

    for (int n = blockIdx.x * 8 + wid; n < N_NODES; n += gridDim.x * 8) {
        int beg = d_rowptr[n], end = d_rowptr[n + 1];
        int deg = end - beg;
        float* od = out + n * OUT_PER_NODE + OFF;
        if (deg == 0) {
            if (lane < 4 * K) od[lane] = 0.0f;
            continue;
        }

        u64 G[K][8];
        #pragma unroll
        for (int k = 0; k < K; k++)
            #pragma unroll
            for (int j = 0; j < 8; j++) G[k][j] = 0ULL;

        // pipelined edge phase (all streams sequential in slot order)
        ulonglong2 p01, p23;
        float2 gpn;
        float4 shn = make_float4(0.f, 0.f, 0.f, 0.f);
        float shn2 = 0.f;
        {
            int s0 = d_srcs[beg];
            const ulonglong2* ap = (const ulonglong2*)&d_Aip[s0 * 4];
            p01 = ap[0]; p23 = ap[1];
            gpn = *(const float2*)&d_g3[beg * 64 + 2 * lane];
            if (L == 1) shn = *(const float4*)&d_sh[beg * 8];
            if (L == 2) { shn2 = d_sh[beg * 8 + 3]; shn = *(const float4*)&d_sh[beg * 8 + 4]; }
        }
        for (int i = beg; i < end; i++) {
            u64 aa[4] = {p01.x, p01.y, p23.x, p23.y};
            float2 gp = gpn;
            float4 shc = shn;
            float shc2 = shn2;
            if (i + 1 < end) {
                int s2 = d_srcs[i + 1];
                const ulonglong2* ap = (const ulonglong2*)&d_Aip[s2 * 4];
                p01 = ap[0]; p23 = ap[1];
                gpn = *(const float2*)&d_g3[(i + 1) * 64 + 2 * lane];
                if (L == 1) shn = *(const float4*)&d_sh[(i + 1) * 8];
                if (L == 2) { shn2 = d_sh[(i + 1) * 8 + 3]; shn = *(const float4*)&d_sh[(i + 1) * 8 + 4]; }
            }

            u64 g00 = pack2(gp.x, gp.x), g11 = pack2(gp.y, gp.y);
            u64 ff[8];
            #pragma unroll
            for (int j = 0; j < 4; j++) { ff[j] = 0ULL; ffma2(ff[j], g00, aa[j]); }
            #pragma unroll
            for (int j = 0; j < 4; j++) { ff[4 + j] = 0ULL; ffma2(ff[4 + j], g11, aa[j]); }

            if (L == 0) {
                #pragma unroll
                for (int j = 0; j < 8; j++) ffma2(G[0][j], ff[j], ONE2);
            } else if (L == 1) {
                float shv[3] = {shc.x, shc.y, shc.z};
                #pragma unroll
                for (int k = 0; k < 3; k++) {
                    u64 ss = pack2(shv[k], shv[k]);
                    #pragma unroll
                    for (int j = 0; j < 8; j++) ffma2(G[k][j], ff[j], ss);
                }
            } else {
                float shv[5] = {shc2, shc.x, shc.y, shc.z, shc.w};
                #pragma unroll
                for (int k = 0; k < 5; k++) {
                    u64 ss = pack2(shv[k], shv[k]);
                    #pragma unroll
                    for (int j = 0; j < 8; j++) ffma2(G[k][j], ff[j], ss);
                }
            }
        }

        float Ad[8];
        {
            const float4* Ai4 = (const float4*)&d_Ai[n * 8];
            float4 b0 = Ai4[0], b1 = Ai4[1];
            Ad[0] = b0.x; Ad[1] = b0.y; Ad[2] = b0.z; Ad[3] = b0.w;
            Ad[4] = b1.x; Ad[5] = b1.y; Ad[6] = b1.z; Ad[7] = b1.w;
        }
        u64 acc[K][2];
        #pragma unroll
        for (int k = 0; k < K; k++) { acc[k][0] = 0ULL; acc[k][1] = 0ULL; }

        #pragma unroll
        for (int j = 0; j < 8; j++) {
            u64 m00, m01, m10, m11;
            {
                int base0 = (lane * 16 + 2 * j) * 32;
                u64 a0 = 0ULL, a1 = 0ULL, b0 = 0ULL, b1 = 0ULL;
                #pragma unroll
                for (int v = 0; v < 8; v++) {
                    u64 ad = pack2(Ad[v], Ad[v]);
                    ulonglong2 mmA =
                        *(const ulonglong2*)&sM[base0 + ((v ^ (lane & 7)) << 2)];
                    ulonglong2 mmB =
                        *(const ulonglong2*)&sM[base0 + 32 + ((v ^ (lane & 7)) << 2)];
                    ffma2(a0, ad, mmA.x);
                    ffma2(a1, ad, mmA.y);
                    ffma2(b0, ad, mmB.x);
                    ffma2(b1, ad, mmB.y);
                }
                m00 = a0; m01 = a1; m10 = b0; m11 = b1;
            }
            #pragma unroll
            for (int k = 0; k < K; k++) {
                float ga, gb; unpack2(G[k][j], ga, gb);
                u64 gaa = pack2(ga, ga), gbb = pack2(gb, gb);
                ffma2(acc[k][0], gaa, m00);
                ffma2(acc[k][1], gaa, m01);
                ffma2(acc[k][0], gbb, m10);
                ffma2(acc[k][1], gbb, m11);
            }
        }

        #pragma unroll
        for (int off = 16; off; off >>= 1) {
            #pragma unroll
            for (int k = 0; k < K; k++) {
                u64 t0 = __shfl_xor_sync(0xffffffffu, acc[k][0], off);
                u64 t1 = __shfl_xor_sync(0xffffffffu, acc[k][1], off);
                ffma2(acc[k][0], t0, ONE2);
                ffma2(acc[k][1], t1, ONE2);
            }
        }

        if (lane == 0) {
            float sc = (1.0f / 64.0f) / (float)deg;
            #pragma unroll
            for (int k = 0; k < K; k++) {
                float W[4];
                unpack2(acc[k][0], W[0], W[1]);
                unpack2(acc[k][1], W[2], W[3]);
                #pragma unroll
                for (int w = 0; w < 4; w++) {
                    if (L == 0)      od[w] = W[w] * sc;
                    else if (L == 1) od[w * 3 + k] = W[w] * sc;
                    else             od[w * 5 + k] = W[w] * sc;
                }
            }
        }
    }
}

// ---------------- launch ----------------
extern "C" void kernel_launch(void* const* d_in, const int* in_sizes, int n_in,
                              void* d_out, int out_size) {
    const float* pos      = (const float*)d_in[0];
    const int*   A        = (const int*)d_in[1];
    const int*   batch    = (const int*)d_in[2];
    const int*   edge_src = (const int*)d_in[3];
    const int*   edge_dst = (const int*)d_in[4];
    const float* shifts   = (const float*)d_in[5];
    const float* cell     = (const float*)d_in[6];
    const float* emb      = (const float*)d_in[7];
    const float* fit_w1   = (const float*)d_in[8];
    const float* fit_b1   = (const float*)d_in[9];
    const float* fit_w2   = (const float*)d_in[10];
    const float* fit_b2   = (const float*)d_in[11];
    const float* fit_w3   = (const float*)d_in[12];
    const float* fit_b3   = (const float*)d_in[13];
    const float* fc_w1    = (const float*)d_in[14];
    const float* fc_w2    = (const float*)d_in[15];
    const float* fc_w3    = (const float*)d_in[16];
    const float* fc_w4    = (const float*)d_in[17];
    float* out = (float*)d_out;

    cudaFuncSetAttribute(k_radial, cudaFuncAttributeMaxDynamicSharedMemorySize,
                         R_SMEM_BYTES);
    cudaFuncSetAttribute(k_main<0>, cudaFuncAttributeMaxDynamicSharedMemorySize, 65536);
    cudaFuncSetAttribute(k_main<1>, cudaFuncAttributeMaxDynamicSharedMemorySize, 65536);
    cudaFuncSetAttribute(k_main<2>, cudaFuncAttributeMaxDynamicSharedMemorySize, 65536);

    k_zero<<<(N_NODES + 255) / 256, 256>>>();
    k_prepcount<<<NODE_BLOCKS + PERM_BLOCKS + (N_EDGES / 256), 256>>>(
        emb, fit_w1, fit_b1, fit_w2, fit_b2, fit_w3, fit_b3, A, fc_w4, edge_dst);
    k_scan<<<1, 1024>>>();
    k_scatter<<<N_EDGES / 256, 256>>>(edge_dst, edge_src);
    k_radial<<<N_EDGES / 128, 256, R_SMEM_BYTES>>>(pos, batch, shifts, cell,
                                                   edge_dst, fc_w1, fc_w2, fc_w3);
    k_main<0><<<444, 256, 65536>>>(out);
    k_main<1><<<296, 256, 65536>>>(out);
    k_main<2><<<296, 256, 65536>>>(out);
}

// round 15
// speedup vs baseline: 1.1520x; 1.1520x over previous
#include <cuda_runtime.h>
#include <math.h>

#define N_NODES 20000
#define N_EDGES 160000
#define OUT_PER_NODE 36
#define SCAN_BLOCKS 79

typedef unsigned long long u64;

__device__ __forceinline__ u64 pack2(float a, float b) {
    u64 r; asm("mov.b64 %0, {%1,%2};" : "=l"(r) : "f"(a), "f"(b)); return r;
}
__device__ __forceinline__ void unpack2(u64 v, float& a, float& b) {
    asm("mov.b64 {%0,%1}, %2;" : "=f"(a), "=f"(b) : "l"(v));
}
__device__ __forceinline__ void ffma2(u64& d, u64 a, u64 b) {
    asm("fma.rn.f32x2 %0, %1, %2, %0;" : "+l"(d) : "l"(a), "l"(b));
}
__device__ __forceinline__ float silu_f(float x) {
    return __fdividef(x, 1.0f + __expf(-x));
}

// ---------------- scratch ----------------
__device__ float d_Ai[N_NODES * 8];
__device__ u64   d_Aip[N_NODES * 4];
__device__ float d_g3[N_EDGES * 64];        // [e][c]  (edge-indexed)
__device__ float d_sh[N_EDGES * 8];
__device__ float d_Ml[3 * 512 * 32];
__device__ int   d_deg[N_NODES];
__device__ int   d_rowptr[N_NODES + 1];
__device__ int   d_fill[N_NODES];
__device__ int   d_csr[N_EDGES];
__device__ int   d_srcs[N_EDGES];
__device__ int   d_bsum[SCAN_BLOCKS];
__device__ int   d_boff[SCAN_BLOCKS];

__global__ void k_zero() {
    int i = blockIdx.x * blockDim.x + threadIdx.x;
    if (i < N_NODES) d_deg[i] = 0;
}

// ---------------- kernel 2: node MLP + M permute + degree count ----------------
#define NODE_BLOCKS 79
#define PERM_BLOCKS 192
__global__ __launch_bounds__(256) void k_prepcount(
    const float* __restrict__ emb_table,
    const float* __restrict__ w1, const float* __restrict__ b1,
    const float* __restrict__ w2, const float* __restrict__ b2,
    const float* __restrict__ w3, const float* __restrict__ b3,
    const int* __restrict__ A,
    const float* __restrict__ fc_w4,
    const int* __restrict__ edge_dst)
{
    int tid = threadIdx.x;
    int bx = blockIdx.x;
    if (bx >= NODE_BLOCKS + PERM_BLOCKS) {
        int e = (bx - NODE_BLOCKS - PERM_BLOCKS) * 256 + tid;
        if (e < N_EDGES) atomicAdd(&d_deg[edge_dst[e]], 1);
        return;
    }
    if (bx >= NODE_BLOCKS) {
        int idx = (bx - NODE_BLOCKS) * 256 + tid;
        int c = idx / 768;
        int rem = idx - c * 768;
        int l = rem / 256;
        int rem2 = rem - l * 256;
        int u = rem2 / 32;
        int vw = rem2 - u * 32;
        d_Ml[l * (512 * 32) + (c * 8 + u) * 32 + vw] = fc_w4[idx];
        return;
    }

    __shared__ __align__(16) float s_w1[16 * 64];
    __shared__ __align__(16) float s_w2[64 * 32];
    __shared__ __align__(16) float s_w3[32 * 8];
    __shared__ float s_b1[64];
    __shared__ float s_b2[32];
    __shared__ float s_b3[8];
    for (int i = tid; i < 16 * 64; i += 256) s_w1[i] = w1[i];
    for (int i = tid; i < 64 * 32; i += 256) s_w2[i] = w2[i];
    for (int i = tid; i < 32 * 8;  i += 256) s_w3[i] = w3[i];
    if (tid < 64) s_b1[tid] = b1[tid];
    if (tid < 32) s_b2[tid] = b2[tid];
    if (tid < 8)  s_b3[tid] = b3[tid];
    __syncthreads();

    int n = bx * 256 + tid;
    if (n >= N_NODES) return;

    int a = A[n];
    float e[16];
    #pragma unroll
    for (int i = 0; i < 16; i++) e[i] = emb_table[a * 16 + i];

    float h1[64];
    #pragma unroll
    for (int j = 0; j < 64; j++) h1[j] = s_b1[j];
    #pragma unroll
    for (int i = 0; i < 16; i++) {
        float ei = e[i];
        #pragma unroll
        for (int j = 0; j < 64; j++) h1[j] += ei * s_w1[i * 64 + j];
    }
    #pragma unroll
    for (int j = 0; j < 64; j++) h1[j] = silu_f(h1[j]);

    float h2[32];
    #pragma unroll
    for (int j = 0; j < 32; j++) h2[j] = s_b2[j];
    #pragma unroll
    for (int i = 0; i < 64; i++) {
        float hi = h1[i];
        #pragma unroll
        for (int j = 0; j < 32; j++) h2[j] += hi * s_w2[i * 32 + j];
    }
    #pragma unroll
    for (int j = 0; j < 32; j++) h2[j] = silu_f(h2[j]);

    float ai[8];
    #pragma unroll
    for (int j = 0; j < 8; j++) ai[j] = s_b3[j];
    #pragma unroll
    for (int i = 0; i < 32; i++) {
        float hi = h2[i];
        #pragma unroll
        for (int j = 0; j < 8; j++) ai[j] += hi * s_w3[i * 8 + j];
    }
    #pragma unroll
    for (int j = 0; j < 8; j++) d_Ai[n * 8 + j] = ai[j];
    #pragma unroll
    for (int j = 0; j < 4; j++) d_Aip[n * 4 + j] = pack2(ai[2 * j], ai[2 * j + 1]);
}

// ---------------- multi-block scan ----------------
__global__ __launch_bounds__(256) void k_scan1() {
    __shared__ int sbuf[256];
    int tid = threadIdx.x;
    int i = blockIdx.x * 256 + tid;
    int v = (i < N_NODES) ? d_deg[i] : 0;
    sbuf[tid] = v;
    __syncthreads();
    #pragma unroll
    for (int off = 1; off < 256; off <<= 1) {
        int t = (tid >= off) ? sbuf[tid - off] : 0;
        __syncthreads();
        sbuf[tid] += t;
        __syncthreads();
    }
    if (i < N_NODES) d_fill[i] = sbuf[tid];      // tmp: inclusive partial
    if (tid == 255) d_bsum[blockIdx.x] = sbuf[255];
}

__global__ __launch_bounds__(128) void k_scan2() {
    __shared__ int sbuf[128];
    int tid = threadIdx.x;
    int v = (tid < SCAN_BLOCKS) ? d_bsum[tid] : 0;
    sbuf[tid] = v;
    __syncthreads();
    #pragma unroll
    for (int off = 1; off < 128; off <<= 1) {
        int t = (tid >= off) ? sbuf[tid - off] : 0;
        __syncthreads();
        sbuf[tid] += t;
        __syncthreads();
    }
    if (tid < SCAN_BLOCKS) d_boff[tid] = sbuf[tid] - v;   // exclusive
}

__global__ __launch_bounds__(256) void k_scan3() {
    int tid = threadIdx.x;
    int i = blockIdx.x * 256 + tid;
    if (i >= N_NODES) return;
    int incl = d_fill[i] + d_boff[blockIdx.x];
    d_rowptr[i + 1] = incl;
    d_fill[i] = incl - d_deg[i];
    if (i == 0) d_rowptr[0] = 0;
}

// ---------------- kernel: scatter edges into CSR (+src gather) ----------------
__global__ void k_scatter(const int* __restrict__ edge_dst,
                          const int* __restrict__ edge_src) {
    int e = blockIdx.x * 256 + threadIdx.x;
    if (e < N_EDGES) {
        int p = atomicAdd(&d_fill[edge_dst[e]], 1);
        d_csr[p] = e;
        d_srcs[p] = edge_src[e];
    }
}

// ---------------- geometry helper ----------------
__device__ __forceinline__ void edge_geom(
    const float* __restrict__ pos, const int* __restrict__ batch,
    const float* __restrict__ shifts, const float* __restrict__ cell,
    int e, int s, int d, float& ex, float& ey, float& ez, float& r)
{
    float sx = shifts[e * 3 + 0], sy = shifts[e * 3 + 1], sz = shifts[e * 3 + 2];
    int b = batch[s];
    const float* C = cell + b * 9;
    float shx = sx * C[0] + sy * C[3] + sz * C[6];
    float shy = sx * C[1] + sy * C[4] + sz * C[7];
    float shz = sx * C[2] + sy * C[5] + sz * C[8];
    ex = pos[d * 3 + 0] - pos[s * 3 + 0] + shx;
    ey = pos[d * 3 + 1] - pos[s * 3 + 1] + shy;
    ez = pos[d * 3 + 2] - pos[s * 3 + 2] + shz;
    r = sqrtf(ex * ex + ey * ey + ez * ez);
}

// ---------------- tiled MLP layer: thread tile 4 edges x 8 outputs ----------------
template<int DEPTH>
__device__ __forceinline__ void gemm_layer(
    const float* __restrict__ inb, float* __restrict__ outb,
    const float* __restrict__ w, float scale, int eg, int og)
{
    const int e0 = eg * 4;
    u64 acc[8][2];
    #pragma unroll
    for (int o = 0; o < 8; o++) { acc[o][0] = 0ULL; acc[o][1] = 0ULL; }

    #pragma unroll 4
    for (int i = 0; i < DEPTH; i++) {
        ulonglong2 a = *(const ulonglong2*)&inb[i * 128 + e0];
        float4 w0 = *(const float4*)&w[i * 64 + og * 8];
        float4 w1 = *(const float4*)&w[i * 64 + og * 8 + 4];
        float wv[8] = {w0.x, w0.y, w0.z, w0.w, w1.x, w1.y, w1.z, w1.w};
        #pragma unroll
        for (int o = 0; o < 8; o++) {
            u64 wd = pack2(wv[o], wv[o]);
            ffma2(acc[o][0], wd, a.x);
            ffma2(acc[o][1], wd, a.y);
        }
    }
    #pragma unroll
    for (int o = 0; o < 8; o++) {
        float f[4];
        unpack2(acc[o][0], f[0], f[1]);
        unpack2(acc[o][1], f[2], f[3]);
        #pragma unroll
        for (int k = 0; k < 4; k++) f[k] = silu_f(f[k] * scale);
        *(float4*)&outb[(og * 8 + o) * 128 + e0] = make_float4(f[0], f[1], f[2], f[3]);
    }
}

// ---------------- kernel: radial chain, edge-indexed, 256 threads ----------------
#define R_W1 0
#define R_W2 1024
#define R_W3 5120
#define R_BA 9216
#define R_BB 17408
#define R_SMEM_BYTES (25600 * 4)

__global__ __launch_bounds__(256) void k_radial(
    const float* __restrict__ pos, const int* __restrict__ batch,
    const float* __restrict__ shifts, const float* __restrict__ cell,
    const int* __restrict__ src_arr, const int* __restrict__ dst_arr,
    const float* __restrict__ fw1, const float* __restrict__ fw2,
    const float* __restrict__ fw3)
{
    extern __shared__ __align__(16) float sm[];
    int tid = threadIdx.x;
    for (int i = tid; i < 1024; i += 256) sm[R_W1 + i] = fw1[i];
    for (int i = tid; i < 4096; i += 256) sm[R_W2 + i] = fw2[i];
    for (int i = tid; i < 4096; i += 256) sm[R_W3 + i] = fw3[i];

    const int e0blk = blockIdx.x * 128;
    if (tid < 128) {
        int e = e0blk + tid;
        int s = src_arr[e];
        int d = dst_arr[e];
        float ex, ey, ez, r;
        edge_geom(pos, batch, shifts, cell, e, s, d, ex, ey, ez, r);

        float inv_r = __fdividef(1.0f, fmaxf(r, 1e-9f));
        float x = ex * inv_r, y = ey * inv_r, z = ez * inv_r;
        const float s3 = 1.7320508075688772f;
        const float s15 = 3.872983346207417f;
        const float s5 = 2.23606797749979f;
        *(float4*)&d_sh[e * 8 + 0] = make_float4(s3 * y, s3 * z, s3 * x, s15 * x * y);
        *(float4*)&d_sh[e * 8 + 4] = make_float4(s15 * y * z,
                                                 0.5f * s5 * (3.0f * z * z - 1.0f),
                                                 s15 * x * z,
                                                 0.5f * s15 * (x * x - y * y));
        const float step = 5.0f / 17.0f;
        const float inv_step = 17.0f / 5.0f;
        const float rb_scale = 4.0f / 1.12f;
        #pragma unroll
        for (int j = 0; j < 16; j++) {
            float c = step * (float)(j + 1);
            float t = (r - c) * inv_step;
            sm[R_BA + j * 128 + tid] = __expf(-t * t) * rb_scale;
        }
    }
    __syncthreads();

    const int eg = tid & 31, og = tid >> 5;

    gemm_layer<16>(sm + R_BA, sm + R_BB, sm + R_W1, 0.25f, eg, og);
    __syncthreads();
    gemm_layer<64>(sm + R_BB, sm + R_BA, sm + R_W2, 0.125f, eg, og);
    __syncthreads();
    gemm_layer<64>(sm + R_BA, sm + R_BB, sm + R_W3, 0.125f, eg, og);
    __syncthreads();

    {
        int le = tid & 127;
        int ch = (tid >> 7) * 32;
        int e = e0blk + le;
        #pragma unroll
        for (int k = 0; k < 8; k++) {
            float4 v = make_float4(sm[R_BB + (ch + k * 4 + 0) * 128 + le],
                                   sm[R_BB + (ch + k * 4 + 1) * 128 + le],
                                   sm[R_BB + (ch + k * 4 + 2) * 128 + le],
                                   sm[R_BB + (ch + k * 4 + 3) * 128 + le]);
            *(float4*)&d_g3[e * 64 + ch + k * 4] = v;
        }
    }
}

// ---------------- kernel: L0 contraction, NB=2 node pairs per warp ----------------
__global__ __launch_bounds__(256, 2) void k_main0(float* __restrict__ out) {
    extern __shared__ float sM[];
    for (int idx = threadIdx.x; idx < 16384; idx += 256) {
        int cu = idx >> 5, vw = idx & 31;
        int v = vw >> 2, w = vw & 3;
        int pv = v ^ ((cu >> 4) & 7);
        sM[(cu << 5) + (pv << 2) + w] = d_Ml[idx];
    }
    __syncthreads();

    const int wid = threadIdx.x >> 5;
    const int lane = threadIdx.x & 31;

    for (int p = blockIdx.x * 8 + wid; p < N_NODES / 2; p += gridDim.x * 8) {
        int n0 = 2 * p;
        int b0 = d_rowptr[n0], m1 = d_rowptr[n0 + 1], e1 = d_rowptr[n0 + 2];

        u64 G0[8], G1[8];
        #pragma unroll
        for (int j = 0; j < 8; j++) { G0[j] = 0ULL; G1[j] = 0ULL; }

        for (int i = b0; i < m1; i++) {
            int e = d_csr[i];
            int s = d_srcs[i];
            const ulonglong2* ap = (const ulonglong2*)&d_Aip[s * 4];
            ulonglong2 a01 = ap[0], a23 = ap[1];
            float2 gp = *(const float2*)&d_g3[e * 64 + 2 * lane];
            u64 g00 = pack2(gp.x, gp.x), g11 = pack2(gp.y, gp.y);
            ffma2(G0[0], g00, a01.x); ffma2(G0[1], g00, a01.y);
            ffma2(G0[2], g00, a23.x); ffma2(G0[3], g00, a23.y);
            ffma2(G0[4], g11, a01.x); ffma2(G0[5], g11, a01.y);
            ffma2(G0[6], g11, a23.x); ffma2(G0[7], g11, a23.y);
        }
        for (int i = m1; i < e1; i++) {
            int e = d_csr[i];
            int s = d_srcs[i];
            const ulonglong2* ap = (const ulonglong2*)&d_Aip[s * 4];
            ulonglong2 a01 = ap[0], a23 = ap[1];
            float2 gp = *(const float2*)&d_g3[e * 64 + 2 * lane];
            u64 g00 = pack2(gp.x, gp.x), g11 = pack2(gp.y, gp.y);
            ffma2(G1[0], g00, a01.x); ffma2(G1[1], g00, a01.y);
            ffma2(G1[2], g00, a23.x); ffma2(G1[3], g00, a23.y);
            ffma2(G1[4], g11, a01.x); ffma2(G1[5], g11, a01.y);
            ffma2(G1[6], g11, a23.x); ffma2(G1[7], g11, a23.y);
        }

        // node phase: M reads shared by both nodes
        float Ad0[8], Ad1[8];
        {
            const float4* A4 = (const float4*)&d_Ai[n0 * 8];
            float4 x0 = A4[0], x1 = A4[1], x2 = A4[2], x3 = A4[3];
            Ad0[0] = x0.x; Ad0[1] = x0.y; Ad0[2] = x0.z; Ad0[3] = x0.w;
            Ad0[4] = x1.x; Ad0[5] = x1.y; Ad0[6] = x1.z; Ad0[7] = x1.w;
            Ad1[0] = x2.x; Ad1[1] = x2.y; Ad1[2] = x2.z; Ad1[3] = x2.w;
            Ad1[4] = x3.x; Ad1[5] = x3.y; Ad1[6] = x3.z; Ad1[7] = x3.w;
        }
        u64 acc0[2] = {0ULL, 0ULL}, acc1[2] = {0ULL, 0ULL};
        #pragma unroll
        for (int j = 0; j < 8; j++) {
            int base0 = (lane * 16 + 2 * j) * 32;
            u64 p00 = 0ULL, p01 = 0ULL, p10 = 0ULL, p11 = 0ULL;
            u64 q00 = 0ULL, q01 = 0ULL, q10 = 0ULL, q11 = 0ULL;
            #pragma unroll
            for (int v = 0; v < 8; v++) {
                ulonglong2 mmA =
                    *(const ulonglong2*)&sM[base0 + ((v ^ (lane & 7)) << 2)];
                ulonglong2 mmB =
                    *(const ulonglong2*)&sM[base0 + 32 + ((v ^ (lane & 7)) << 2)];
                u64 ad0 = pack2(Ad0[v], Ad0[v]);
                u64 ad1 = pack2(Ad1[v], Ad1[v]);
                ffma2(p00, ad0, mmA.x); ffma2(p01, ad0, mmA.y);
                ffma2(p10, ad0, mmB.x); ffma2(p11, ad0, mmB.y);
                ffma2(q00, ad1, mmA.x); ffma2(q01, ad1, mmA.y);
                ffma2(q10, ad1, mmB.x); ffma2(q11, ad1, mmB.y);
            }
            float ga, gb;
            unpack2(G0[j], ga, gb);
            {
                u64 gaa = pack2(ga, ga), gbb = pack2(gb, gb);
                ffma2(acc0[0], gaa, p00); ffma2(acc0[1], gaa, p01);
                ffma2(acc0[0], gbb, p10); ffma2(acc0[1], gbb, p11);
            }
            unpack2(G1[j], ga, gb);
            {
                u64 gaa = pack2(ga, ga), gbb = pack2(gb, gb);
                ffma2(acc1[0], gaa, q00); ffma2(acc1[1], gaa, q01);
                ffma2(acc1[0], gbb, q10); ffma2(acc1[1], gbb, q11);
            }
        }

        const u64 ONE2 = pack2(1.0f, 1.0f);
        #pragma unroll
        for (int off = 16; off; off >>= 1) {
            u64 t0 = __shfl_xor_sync(0xffffffffu, acc0[0], off);
            u64 t1 = __shfl_xor_sync(0xffffffffu, acc0[1], off);
            u64 t2 = __shfl_xor_sync(0xffffffffu, acc1[0], off);
            u64 t3 = __shfl_xor_sync(0xffffffffu, acc1[1], off);
            ffma2(acc0[0], t0, ONE2);
            ffma2(acc0[1], t1, ONE2);
            ffma2(acc1[0], t2, ONE2);
            ffma2(acc1[1], t3, ONE2);
        }

        if (lane == 0) {
            int d0 = m1 - b0, d1 = e1 - m1;
            float sc0 = (1.0f / 64.0f) / (float)(d0 > 0 ? d0 : 1);
            float sc1 = (1.0f / 64.0f) / (float)(d1 > 0 ? d1 : 1);
            float W[4];
            unpack2(acc0[0], W[0], W[1]);
            unpack2(acc0[1], W[2], W[3]);
            #pragma unroll
            for (int w = 0; w < 4; w++) out[n0 * OUT_PER_NODE + w] = W[w] * sc0;
            unpack2(acc1[0], W[0], W[1]);
            unpack2(acc1[1], W[2], W[3]);
            #pragma unroll
            for (int w = 0; w < 4; w++) out[(n0 + 1) * OUT_PER_NODE + w] = W[w] * sc1;
        }
    }
}

// ---------------- kernel: L=1,2 contraction, warp-per-node ----------------
template<int L>
__global__ __launch_bounds__(256, 2) void k_main(float* __restrict__ out)
{
    constexpr int K   = (L == 1) ? 3 : 5;
    constexpr int OFF = (L == 1) ? 4 : 16;
    extern __shared__ float sM[];

    for (int idx = threadIdx.x; idx < 16384; idx += 256) {
        int cu = idx >> 5, vw = idx & 31;
        int v = vw >> 2, w = vw & 3;
        int pv = v ^ ((cu >> 4) & 7);
        sM[(cu << 5) + (pv << 2) + w] = d_Ml[L * 16384 + idx];
    }
    __syncthreads();

    const int wid = threadIdx.x >> 5;
    const int lane = threadIdx.x & 31;
    const u64 ONE2 = pack2(1.0f, 1.0f);

    for (int n = blockIdx.x * 8 + wid; n < N_NODES; n += gridDim.x * 8) {
        int beg = d_rowptr[n], end = d_rowptr[n + 1];
        int deg = end - beg;
        float* od = out + n * OUT_PER_NODE + OFF;
        if (deg == 0) {
            if (lane < 4 * K) od[lane] = 0.0f;
            continue;
        }

        u64 G[K][8];
        #pragma unroll
        for (int k = 0; k < K; k++)
            #pragma unroll
            for (int j = 0; j < 8; j++) G[k][j] = 0ULL;

        ulonglong2 p01, p23;
        float2 gpn;
        float4 shn = make_float4(0.f, 0.f, 0.f, 0.f);
        float shn2 = 0.f;
        {
            int e0 = d_csr[beg];
            int s0 = d_srcs[beg];
            const ulonglong2* ap = (const ulonglong2*)&d_Aip[s0 * 4];
            p01 = ap[0]; p23 = ap[1];
            gpn = *(const float2*)&d_g3[e0 * 64 + 2 * lane];
            if (L == 1) shn = *(const float4*)&d_sh[e0 * 8];
            if (L == 2) { shn2 = d_sh[e0 * 8 + 3]; shn = *(const float4*)&d_sh[e0 * 8 + 4]; }
        }
        for (int i = beg; i < end; i++) {
            u64 aa[4] = {p01.x, p01.y, p23.x, p23.y};
            float2 gp = gpn;
            float4 shc = shn;
            float shc2 = shn2;
            if (i + 1 < end) {
                int e2 = d_csr[i + 1];
                int s2 = d_srcs[i + 1];
                const ulonglong2* ap = (const ulonglong2*)&d_Aip[s2 * 4];
                p01 = ap[0]; p23 = ap[1];
                gpn = *(const float2*)&d_g3[e2 * 64 + 2 * lane];
                if (L == 1) shn = *(const float4*)&d_sh[e2 * 8];
                if (L == 2) { shn2 = d_sh[e2 * 8 + 3]; shn = *(const float4*)&d_sh[e2 * 8 + 4]; }
            }

            u64 g00 = pack2(gp.x, gp.x), g11 = pack2(gp.y, gp.y);
            u64 ff[8];
            #pragma unroll
            for (int j = 0; j < 4; j++) { ff[j] = 0ULL; ffma2(ff[j], g00, aa[j]); }
            #pragma unroll
            for (int j = 0; j < 4; j++) { ff[4 + j] = 0ULL; ffma2(ff[4 + j], g11, aa[j]); }

            if (L == 1) {
                float shv[3] = {shc.x, shc.y, shc.z};
                #pragma unroll
                for (int k = 0; k < 3; k++) {
                    u64 ss = pack2(shv[k], shv[k]);
                    #pragma unroll
                    for (int j = 0; j < 8; j++) ffma2(G[k][j], ff[j], ss);
                }
            } else {
                float shv[5] = {shc2, shc.x, shc.y, shc.z, shc.w};
                #pragma unroll
                for (int k = 0; k < 5; k++) {
                    u64 ss = pack2(shv[k], shv[k]);
                    #pragma unroll
                    for (int j = 0; j < 8; j++) ffma2(G[k][j], ff[j], ss);
                }
            }
        }

        float Ad[8];
        {
            const float4* Ai4 = (const float4*)&d_Ai[n * 8];
            float4 b0 = Ai4[0], b1 = Ai4[1];
            Ad[0] = b0.x; Ad[1] = b0.y; Ad[2] = b0.z; Ad[3] = b0.w;
            Ad[4] = b1.x; Ad[5] = b1.y; Ad[6] = b1.z; Ad[7] = b1.w;
        }
        u64 acc[K][2];
        #pragma unroll
        for (int k = 0; k < K; k++) { acc[k][0] = 0ULL; acc[k][1] = 0ULL; }

        #pragma unroll
        for (int j = 0; j < 8; j++) {
            u64 m00, m01, m10, m11;
            {
                int base0 = (lane * 16 + 2 * j) * 32;
                u64 a0 = 0ULL, a1 = 0ULL, b0 = 0ULL, b1 = 0ULL;
                #pragma unroll
                for (int v = 0; v < 8; v++) {
                    u64 ad = pack2(Ad[v], Ad[v]);
                    ulonglong2 mmA =
                        *(const ulonglong2*)&sM[base0 + ((v ^ (lane & 7)) << 2)];
                    ulonglong2 mmB =
                        *(const ulonglong2*)&sM[base0 + 32 + ((v ^ (lane & 7)) << 2)];
                    ffma2(a0, ad, mmA.x);
                    ffma2(a1, ad, mmA.y);
                    ffma2(b0, ad, mmB.x);
                    ffma2(b1, ad, mmB.y);
                }
                m00 = a0; m01 = a1; m10 = b0; m11 = b1;
            }
            #pragma unroll
            for (int k = 0; k < K; k++) {
                float ga, gb; unpack2(G[k][j], ga, gb);
                u64 gaa = pack2(ga, ga), gbb = pack2(gb, gb);
                ffma2(acc[k][0], gaa, m00);
                ffma2(acc[k][1], gaa, m01);
                ffma2(acc[k][0], gbb, m10);
                ffma2(acc[k][1], gbb, m11);
            }
        }

        #pragma unroll
        for (int off = 16; off; off >>= 1) {
            #pragma unroll
            for (int k = 0; k < K; k++) {
                u64 t0 = __shfl_xor_sync(0xffffffffu, acc[k][0], off);
                u64 t1 = __shfl_xor_sync(0xffffffffu, acc[k][1], off);
                ffma2(acc[k][0], t0, ONE2);
                ffma2(acc[k][1], t1, ONE2);
            }
        }

        if (lane == 0) {
            float sc = (1.0f / 64.0f) / (float)deg;
            #pragma unroll
            for (int k = 0; k < K; k++) {
                float W[4];
                unpack2(acc[k][0], W[0], W[1]);
                unpack2(acc[k][1], W[2], W[3]);
                #pragma unroll
                for (int w = 0; w < 4; w++) {
                    if (L == 1) od[w * 3 + k] = W[w] * sc;
                    else        od[w * 5 + k] = W[w] * sc;
                }
            }
        }
    }
}

// ---------------- launch ----------------
extern "C" void kernel_launch(void* const* d_in, const int* in_sizes, int n_in,
                              void* d_out, int out_size) {
    const float* pos      = (const float*)d_in[0];
    const int*   A        = (const int*)d_in[1];
    const int*   batch    = (const int*)d_in[2];
    const int*   edge_src = (const int*)d_in[3];
    const int*   edge_dst = (const int*)d_in[4];
    const float* shifts   = (const float*)d_in[5];
    const float* cell     = (const float*)d_in[6];
    const float* emb      = (const float*)d_in[7];
    const float* fit_w1   = (const float*)d_in[8];
    const float* fit_b1   = (const float*)d_in[9];
    const float* fit_w2   = (const float*)d_in[10];
    const float* fit_b2   = (const float*)d_in[11];
    const float* fit_w3   = (const float*)d_in[12];
    const float* fit_b3   = (const float*)d_in[13];
    const float* fc_w1    = (const float*)d_in[14];
    const float* fc_w2    = (const float*)d_in[15];
    const float* fc_w3    = (const float*)d_in[16];
    const float* fc_w4    = (const float*)d_in[17];
    float* out = (float*)d_out;

    cudaFuncSetAttribute(k_radial, cudaFuncAttributeMaxDynamicSharedMemorySize,
                         R_SMEM_BYTES);
    cudaFuncSetAttribute(k_main0,  cudaFuncAttributeMaxDynamicSharedMemorySize, 65536);
    cudaFuncSetAttribute(k_main<1>, cudaFuncAttributeMaxDynamicSharedMemorySize, 65536);
    cudaFuncSetAttribute(k_main<2>, cudaFuncAttributeMaxDynamicSharedMemorySize, 65536);

    // order: radial is the 4th launch (ncu capture slot); scans fill in around it
    k_zero<<<(N_NODES + 255) / 256, 256>>>();
    k_prepcount<<<NODE_BLOCKS + PERM_BLOCKS + (N_EDGES / 256), 256>>>(
        emb, fit_w1, fit_b1, fit_w2, fit_b2, fit_w3, fit_b3, A, fc_w4, edge_dst);
    k_scan1<<<SCAN_BLOCKS, 256>>>();
    k_radial<<<N_EDGES / 128, 256, R_SMEM_BYTES>>>(pos, batch, shifts, cell,
                                                   edge_src, edge_dst,
                                                   fc_w1, fc_w2, fc_w3);
    k_scan2<<<1, 128>>>();
    k_scan3<<<SCAN_BLOCKS, 256>>>();
    k_scatter<<<N_EDGES / 256, 256>>>(edge_dst, edge_src);
    k_main0<<<296, 256, 65536>>>(out);
    k_main<1><<<296, 256, 65536>>>(out);
    k_main<2><<<296, 256, 65536>>>(out);
}

// round 16
// speedup vs baseline: 1.1613x; 1.0081x over previous
#include <cuda_runtime.h>
#include <math.h>

#define N_NODES 20000
#define N_EDGES 160000
#define OUT_PER_NODE 36
#define SCAN_BLOCKS 79

typedef unsigned long long u64;

__device__ __forceinline__ u64 pack2(float a, float b) {
    u64 r; asm("mov.b64 %0, {%1,%2};" : "=l"(r) : "f"(a), "f"(b)); return r;
}
__device__ __forceinline__ void unpack2(u64 v, float& a, float& b) {
    asm("mov.b64 {%0,%1}, %2;" : "=f"(a), "=f"(b) : "l"(v));
}
__device__ __forceinline__ void ffma2(u64& d, u64 a, u64 b) {
    asm("fma.rn.f32x2 %0, %1, %2, %0;" : "+l"(d) : "l"(a), "l"(b));
}
__device__ __forceinline__ float silu_f(float x) {
    return __fdividef(x, 1.0f + __expf(-x));
}

// ---------------- scratch ----------------
__device__ float d_Ai[N_NODES * 8];
__device__ u64   d_Aip[N_NODES * 4];
__device__ float d_g3[N_EDGES * 64];        // [e][c]  (edge-indexed)
__device__ float d_sh[N_EDGES * 8];
__device__ float d_Ml[3 * 512 * 32];
__device__ int   d_deg[N_NODES];
__device__ int   d_rowptr[N_NODES + 1];
__device__ int   d_fill[N_NODES];
__device__ int   d_csr[N_EDGES];
__device__ int   d_srcs[N_EDGES];
__device__ int   d_bsum[SCAN_BLOCKS];
__device__ int   d_boff[SCAN_BLOCKS];

__global__ void k_zero() {
    int i = blockIdx.x * blockDim.x + threadIdx.x;
    if (i < N_NODES) d_deg[i] = 0;
}

// ---------------- kernel 2: node MLP + M permute + degree count ----------------
#define NODE_BLOCKS 79
#define PERM_BLOCKS 192
__global__ __launch_bounds__(256) void k_prepcount(
    const float* __restrict__ emb_table,
    const float* __restrict__ w1, const float* __restrict__ b1,
    const float* __restrict__ w2, const float* __restrict__ b2,
    const float* __restrict__ w3, const float* __restrict__ b3,
    const int* __restrict__ A,
    const float* __restrict__ fc_w4,
    const int* __restrict__ edge_dst)
{
    int tid = threadIdx.x;
    int bx = blockIdx.x;
    if (bx >= NODE_BLOCKS + PERM_BLOCKS) {
        int e = (bx - NODE_BLOCKS - PERM_BLOCKS) * 256 + tid;
        if (e < N_EDGES) atomicAdd(&d_deg[edge_dst[e]], 1);
        return;
    }
    if (bx >= NODE_BLOCKS) {
        int idx = (bx - NODE_BLOCKS) * 256 + tid;
        int c = idx / 768;
        int rem = idx - c * 768;
        int l = rem / 256;
        int rem2 = rem - l * 256;
        int u = rem2 / 32;
        int vw = rem2 - u * 32;
        d_Ml[l * (512 * 32) + (c * 8 + u) * 32 + vw] = fc_w4[idx];
        return;
    }

    __shared__ __align__(16) float s_w1[16 * 64];
    __shared__ __align__(16) float s_w2[64 * 32];
    __shared__ __align__(16) float s_w3[32 * 8];
    __shared__ float s_b1[64];
    __shared__ float s_b2[32];
    __shared__ float s_b3[8];
    for (int i = tid; i < 16 * 64; i += 256) s_w1[i] = w1[i];
    for (int i = tid; i < 64 * 32; i += 256) s_w2[i] = w2[i];
    for (int i = tid; i < 32 * 8;  i += 256) s_w3[i] = w3[i];
    if (tid < 64) s_b1[tid] = b1[tid];
    if (tid < 32) s_b2[tid] = b2[tid];
    if (tid < 8)  s_b3[tid] = b3[tid];
    __syncthreads();

    int n = bx * 256 + tid;
    if (n >= N_NODES) return;

    int a = A[n];
    float e[16];
    #pragma unroll
    for (int i = 0; i < 16; i++) e[i] = emb_table[a * 16 + i];

    float h1[64];
    #pragma unroll
    for (int j = 0; j < 64; j++) h1[j] = s_b1[j];
    #pragma unroll
    for (int i = 0; i < 16; i++) {
        float ei = e[i];
        #pragma unroll
        for (int j = 0; j < 64; j++) h1[j] += ei * s_w1[i * 64 + j];
    }
    #pragma unroll
    for (int j = 0; j < 64; j++) h1[j] = silu_f(h1[j]);

    float h2[32];
    #pragma unroll
    for (int j = 0; j < 32; j++) h2[j] = s_b2[j];
    #pragma unroll
    for (int i = 0; i < 64; i++) {
        float hi = h1[i];
        #pragma unroll
        for (int j = 0; j < 32; j++) h2[j] += hi * s_w2[i * 32 + j];
    }
    #pragma unroll
    for (int j = 0; j < 32; j++) h2[j] = silu_f(h2[j]);

    float ai[8];
    #pragma unroll
    for (int j = 0; j < 8; j++) ai[j] = s_b3[j];
    #pragma unroll
    for (int i = 0; i < 32; i++) {
        float hi = h2[i];
        #pragma unroll
        for (int j = 0; j < 8; j++) ai[j] += hi * s_w3[i * 8 + j];
    }
    #pragma unroll
    for (int j = 0; j < 8; j++) d_Ai[n * 8 + j] = ai[j];
    #pragma unroll
    for (int j = 0; j < 4; j++) d_Aip[n * 4 + j] = pack2(ai[2 * j], ai[2 * j + 1]);
}

// ---------------- multi-block scan ----------------
__global__ __launch_bounds__(256) void k_scan1() {
    __shared__ int sbuf[256];
    int tid = threadIdx.x;
    int i = blockIdx.x * 256 + tid;
    int v = (i < N_NODES) ? d_deg[i] : 0;
    sbuf[tid] = v;
    __syncthreads();
    #pragma unroll
    for (int off = 1; off < 256; off <<= 1) {
        int t = (tid >= off) ? sbuf[tid - off] : 0;
        __syncthreads();
        sbuf[tid] += t;
        __syncthreads();
    }
    if (i < N_NODES) d_fill[i] = sbuf[tid];
    if (tid == 255) d_bsum[blockIdx.x] = sbuf[255];
}

__global__ __launch_bounds__(128) void k_scan2() {
    __shared__ int sbuf[128];
    int tid = threadIdx.x;
    int v = (tid < SCAN_BLOCKS) ? d_bsum[tid] : 0;
    sbuf[tid] = v;
    __syncthreads();
    #pragma unroll
    for (int off = 1; off < 128; off <<= 1) {
        int t = (tid >= off) ? sbuf[tid - off] : 0;
        __syncthreads();
        sbuf[tid] += t;
        __syncthreads();
    }
    if (tid < SCAN_BLOCKS) d_boff[tid] = sbuf[tid] - v;
}

__global__ __launch_bounds__(256) void k_scan3() {
    int tid = threadIdx.x;
    int i = blockIdx.x * 256 + tid;
    if (i >= N_NODES) return;
    int incl = d_fill[i] + d_boff[blockIdx.x];
    d_rowptr[i + 1] = incl;
    d_fill[i] = incl - d_deg[i];
    if (i == 0) d_rowptr[0] = 0;
}

// ---------------- kernel: scatter edges into CSR (+src gather) ----------------
__global__ void k_scatter(const int* __restrict__ edge_dst,
                          const int* __restrict__ edge_src) {
    int e = blockIdx.x * 256 + threadIdx.x;
    if (e < N_EDGES) {
        int p = atomicAdd(&d_fill[edge_dst[e]], 1);
        d_csr[p] = e;
        d_srcs[p] = edge_src[e];
    }
}

// ---------------- geometry helper ----------------
__device__ __forceinline__ void edge_geom(
    const float* __restrict__ pos, const int* __restrict__ batch,
    const float* __restrict__ shifts, const float* __restrict__ cell,
    int e, int s, int d, float& ex, float& ey, float& ez, float& r)
{
    float sx = shifts[e * 3 + 0], sy = shifts[e * 3 + 1], sz = shifts[e * 3 + 2];
    int b = batch[s];
    const float* C = cell + b * 9;
    float shx = sx * C[0] + sy * C[3] + sz * C[6];
    float shy = sx * C[1] + sy * C[4] + sz * C[7];
    float shz = sx * C[2] + sy * C[5] + sz * C[8];
    ex = pos[d * 3 + 0] - pos[s * 3 + 0] + shx;
    ey = pos[d * 3 + 1] - pos[s * 3 + 1] + shy;
    ez = pos[d * 3 + 2] - pos[s * 3 + 2] + shz;
    r = sqrtf(ex * ex + ey * ey + ez * ez);
}

// ---------------- tiled MLP layer, 512 threads: 2 edges x 8 outputs ----------------
// f32x2 lanes = output pairs (weights load pre-packed); eg in [0,64), og in [0,8)
template<int DEPTH>
__device__ __forceinline__ void gemm_layer2(
    const float* __restrict__ inb, float* __restrict__ outb,
    const float* __restrict__ w, float scale, int eg, int og)
{
    const int e0 = eg * 2;
    u64 acc[2][4];
    #pragma unroll
    for (int e = 0; e < 2; e++)
        #pragma unroll
        for (int j = 0; j < 4; j++) acc[e][j] = 0ULL;

    #pragma unroll 4
    for (int i = 0; i < DEPTH; i++) {
        float2 a = *(const float2*)&inb[i * 128 + e0];
        ulonglong2 wp0 = *(const ulonglong2*)&w[i * 64 + og * 8];
        ulonglong2 wp1 = *(const ulonglong2*)&w[i * 64 + og * 8 + 4];
        u64 aa0 = pack2(a.x, a.x);
        u64 aa1 = pack2(a.y, a.y);
        ffma2(acc[0][0], aa0, wp0.x);
        ffma2(acc[0][1], aa0, wp0.y);
        ffma2(acc[0][2], aa0, wp1.x);
        ffma2(acc[0][3], aa0, wp1.y);
        ffma2(acc[1][0], aa1, wp0.x);
        ffma2(acc[1][1], aa1, wp0.y);
        ffma2(acc[1][2], aa1, wp1.x);
        ffma2(acc[1][3], aa1, wp1.y);
    }
    #pragma unroll
    for (int j = 0; j < 4; j++) {
        float f00, f01, f10, f11;
        unpack2(acc[0][j], f00, f01);   // edge e0: outputs 2j, 2j+1
        unpack2(acc[1][j], f10, f11);   // edge e0+1
        f00 = silu_f(f00 * scale);
        f01 = silu_f(f01 * scale);
        f10 = silu_f(f10 * scale);
        f11 = silu_f(f11 * scale);
        *(float2*)&outb[(og * 8 + 2 * j + 0) * 128 + e0] = make_float2(f00, f10);
        *(float2*)&outb[(og * 8 + 2 * j + 1) * 128 + e0] = make_float2(f01, f11);
    }
}

// ---------------- kernel: radial chain, 512 threads, 128-edge tile ----------------
#define R_W1 0
#define R_W2 1024
#define R_W3 5120
#define R_BA 9216
#define R_BB 17408
#define R_SMEM_BYTES (25600 * 4)

__global__ __launch_bounds__(512) void k_radial(
    const float* __restrict__ pos, const int* __restrict__ batch,
    const float* __restrict__ shifts, const float* __restrict__ cell,
    const int* __restrict__ src_arr, const int* __restrict__ dst_arr,
    const float* __restrict__ fw1, const float* __restrict__ fw2,
    const float* __restrict__ fw3)
{
    extern __shared__ __align__(16) float sm[];
    int tid = threadIdx.x;
    for (int i = tid; i < 1024; i += 512) sm[R_W1 + i] = fw1[i];
    for (int i = tid; i < 4096; i += 512) sm[R_W2 + i] = fw2[i];
    for (int i = tid; i < 4096; i += 512) sm[R_W3 + i] = fw3[i];

    const int e0blk = blockIdx.x * 128;
    if (tid < 128) {
        int e = e0blk + tid;
        int s = src_arr[e];
        int d = dst_arr[e];
        float ex, ey, ez, r;
        edge_geom(pos, batch, shifts, cell, e, s, d, ex, ey, ez, r);

        float inv_r = __fdividef(1.0f, fmaxf(r, 1e-9f));
        float x = ex * inv_r, y = ey * inv_r, z = ez * inv_r;
        const float s3 = 1.7320508075688772f;
        const float s15 = 3.872983346207417f;
        const float s5 = 2.23606797749979f;
        *(float4*)&d_sh[e * 8 + 0] = make_float4(s3 * y, s3 * z, s3 * x, s15 * x * y);
        *(float4*)&d_sh[e * 8 + 4] = make_float4(s15 * y * z,
                                                 0.5f * s5 * (3.0f * z * z - 1.0f),
                                                 s15 * x * z,
                                                 0.5f * s15 * (x * x - y * y));
        const float step = 5.0f / 17.0f;
        const float inv_step = 17.0f / 5.0f;
        const float rb_scale = 4.0f / 1.12f;
        #pragma unroll
        for (int j = 0; j < 16; j++) {
            float c = step * (float)(j + 1);
            float t = (r - c) * inv_step;
            sm[R_BA + j * 128 + tid] = __expf(-t * t) * rb_scale;
        }
    }
    __syncthreads();

    const int eg = tid & 63, og = tid >> 6;

    gemm_layer2<16>(sm + R_BA, sm + R_BB, sm + R_W1, 0.25f, eg, og);
    __syncthreads();
    gemm_layer2<64>(sm + R_BB, sm + R_BA, sm + R_W2, 0.125f, eg, og);
    __syncthreads();
    gemm_layer2<64>(sm + R_BA, sm + R_BB, sm + R_W3, 0.125f, eg, og);
    __syncthreads();

    {
        int le = tid & 127;
        int ch = (tid >> 7) * 16;        // 0,16,32,48
        int e = e0blk + le;
        #pragma unroll
        for (int k = 0; k < 4; k++) {
            float4 v = make_float4(sm[R_BB + (ch + k * 4 + 0) * 128 + le],
                                   sm[R_BB + (ch + k * 4 + 1) * 128 + le],
                                   sm[R_BB + (ch + k * 4 + 2) * 128 + le],
                                   sm[R_BB + (ch + k * 4 + 3) * 128 + le]);
            *(float4*)&d_g3[e * 64 + ch + k * 4] = v;
        }
    }
}

// ---------------- kernel: L0 contraction, NB=2 node pairs per warp ----------------
__global__ __launch_bounds__(256, 2) void k_main0(float* __restrict__ out) {
    extern __shared__ float sM[];
    for (int idx = threadIdx.x; idx < 16384; idx += 256) {
        int cu = idx >> 5, vw = idx & 31;
        int v = vw >> 2, w = vw & 3;
        int pv = v ^ ((cu >> 4) & 7);
        sM[(cu << 5) + (pv << 2) + w] = d_Ml[idx];
    }
    __syncthreads();

    const int wid = threadIdx.x >> 5;
    const int lane = threadIdx.x & 31;

    for (int p = blockIdx.x * 8 + wid; p < N_NODES / 2; p += gridDim.x * 8) {
        int n0 = 2 * p;
        int b0 = d_rowptr[n0], m1 = d_rowptr[n0 + 1], e1 = d_rowptr[n0 + 2];

        u64 G0[8], G1[8];
        #pragma unroll
        for (int j = 0; j < 8; j++) { G0[j] = 0ULL; G1[j] = 0ULL; }

        for (int i = b0; i < m1; i++) {
            int e = d_csr[i];
            int s = d_srcs[i];
            const ulonglong2* ap = (const ulonglong2*)&d_Aip[s * 4];
            ulonglong2 a01 = ap[0], a23 = ap[1];
            float2 gp = *(const float2*)&d_g3[e * 64 + 2 * lane];
            u64 g00 = pack2(gp.x, gp.x), g11 = pack2(gp.y, gp.y);
            ffma2(G0[0], g00, a01.x); ffma2(G0[1], g00, a01.y);
            ffma2(G0[2], g00, a23.x); ffma2(G0[3], g00, a23.y);
            ffma2(G0[4], g11, a01.x); ffma2(G0[5], g11, a01.y);
            ffma2(G0[6], g11, a23.x); ffma2(G0[7], g11, a23.y);
        }
        for (int i = m1; i < e1; i++) {
            int e = d_csr[i];
            int s = d_srcs[i];
            const ulonglong2* ap = (const ulonglong2*)&d_Aip[s * 4];
            ulonglong2 a01 = ap[0], a23 = ap[1];
            float2 gp = *(const float2*)&d_g3[e * 64 + 2 * lane];
            u64 g00 = pack2(gp.x, gp.x), g11 = pack2(gp.y, gp.y);
            ffma2(G1[0], g00, a01.x); ffma2(G1[1], g00, a01.y);
            ffma2(G1[2], g00, a23.x); ffma2(G1[3], g00, a23.y);
            ffma2(G1[4], g11, a01.x); ffma2(G1[5], g11, a01.y);
            ffma2(G1[6], g11, a23.x); ffma2(G1[7], g11, a23.y);
        }

        float Ad0[8], Ad1[8];
        {
            const float4* A4 = (const float4*)&d_Ai[n0 * 8];
            float4 x0 = A4[0], x1 = A4[1], x2 = A4[2], x3 = A4[3];
            Ad0[0] = x0.x; Ad0[1] = x0.y; Ad0[2] = x0.z; Ad0[3] = x0.w;
            Ad0[4] = x1.x; Ad0[5] = x1.y; Ad0[6] = x1.z; Ad0[7] = x1.w;
            Ad1[0] = x2.x; Ad1[1] = x2.y; Ad1[2] = x2.z; Ad1[3] = x2.w;
            Ad1[4] = x3.x; Ad1[5] = x3.y; Ad1[6] = x3.z; Ad1[7] = x3.w;
        }
        u64 acc0[2] = {0ULL, 0ULL}, acc1[2] = {0ULL, 0ULL};
        #pragma unroll
        for (int j = 0; j < 8; j++) {
            int base0 = (lane * 16 + 2 * j) * 32;
            u64 p00 = 0ULL, p01 = 0ULL, p10 = 0ULL, p11 = 0ULL;
            u64 q00 = 0ULL, q01 = 0ULL, q10 = 0ULL, q11 = 0ULL;
            #pragma unroll
            for (int v = 0; v < 8; v++) {
                ulonglong2 mmA =
                    *(const ulonglong2*)&sM[base0 + ((v ^ (lane & 7)) << 2)];
                ulonglong2 mmB =
                    *(const ulonglong2*)&sM[base0 + 32 + ((v ^ (lane & 7)) << 2)];
                u64 ad0 = pack2(Ad0[v], Ad0[v]);
                u64 ad1 = pack2(Ad1[v], Ad1[v]);
                ffma2(p00, ad0, mmA.x); ffma2(p01, ad0, mmA.y);
                ffma2(p10, ad0, mmB.x); ffma2(p11, ad0, mmB.y);
                ffma2(q00, ad1, mmA.x); ffma2(q01, ad1, mmA.y);
                ffma2(q10, ad1, mmB.x); ffma2(q11, ad1, mmB.y);
            }
            float ga, gb;
            unpack2(G0[j], ga, gb);
            {
                u64 gaa = pack2(ga, ga), gbb = pack2(gb, gb);
                ffma2(acc0[0], gaa, p00); ffma2(acc0[1], gaa, p01);
                ffma2(acc0[0], gbb, p10); ffma2(acc0[1], gbb, p11);
            }
            unpack2(G1[j], ga, gb);
            {
                u64 gaa = pack2(ga, ga), gbb = pack2(gb, gb);
                ffma2(acc1[0], gaa, q00); ffma2(acc1[1], gaa, q01);
                ffma2(acc1[0], gbb, q10); ffma2(acc1[1], gbb, q11);
            }
        }

        const u64 ONE2 = pack2(1.0f, 1.0f);
        #pragma unroll
        for (int off = 16; off; off >>= 1) {
            u64 t0 = __shfl_xor_sync(0xffffffffu, acc0[0], off);
            u64 t1 = __shfl_xor_sync(0xffffffffu, acc0[1], off);
            u64 t2 = __shfl_xor_sync(0xffffffffu, acc1[0], off);
            u64 t3 = __shfl_xor_sync(0xffffffffu, acc1[1], off);
            ffma2(acc0[0], t0, ONE2);
            ffma2(acc0[1], t1, ONE2);
            ffma2(acc1[0], t2, ONE2);
            ffma2(acc1[1], t3, ONE2);
        }

        if (lane == 0) {
            int d0 = m1 - b0, d1 = e1 - m1;
            float sc0 = (1.0f / 64.0f) / (float)(d0 > 0 ? d0 : 1);
            float sc1 = (1.0f / 64.0f) / (float)(d1 > 0 ? d1 : 1);
            float W[4];
            unpack2(acc0[0], W[0], W[1]);
            unpack2(acc0[1], W[2], W[3]);
            #pragma unroll
            for (int w = 0; w < 4; w++) out[n0 * OUT_PER_NODE + w] = W[w] * sc0;
            unpack2(acc1[0], W[0], W[1]);
            unpack2(acc1[1], W[2], W[3]);
            #pragma unroll
            for (int w = 0; w < 4; w++) out[(n0 + 1) * OUT_PER_NODE + w] = W[w] * sc1;
        }
    }
}

// ---------------- kernel: L=1,2 contraction, warp-per-node ----------------
template<int L>
__global__ __launch_bounds__(256, 2) void k_main(float* __restrict__ out)
{
    constexpr int K   = (L == 1) ? 3 : 5;
    constexpr int OFF = (L == 1) ? 4 : 16;
    extern __shared__ float sM[];

    for (int idx = threadIdx.x; idx < 16384; idx += 256) {
        int cu = idx >> 5, vw = idx & 31;
        int v = vw >> 2, w = vw & 3;
        int pv = v ^ ((cu >> 4) & 7);
        sM[(cu << 5) + (pv << 2) + w] = d_Ml[L * 16384 + idx];
    }
    __syncthreads();

    const int wid = threadIdx.x >> 5;
    const int lane = threadIdx.x & 31;
    const u64 ONE2 = pack2(1.0f, 1.0f);

    for (int n = blockIdx.x * 8 + wid; n < N_NODES; n += gridDim.x * 8) {
        int beg = d_rowptr[n], end = d_rowptr[n + 1];
        int deg = end - beg;
        float* od = out + n * OUT_PER_NODE + OFF;
        if (deg == 0) {
            if (lane < 4 * K) od[lane] = 0.0f;
            continue;
        }

        u64 G[K][8];
        #pragma unroll
        for (int k = 0; k < K; k++)
            #pragma unroll
            for (int j = 0; j < 8; j++) G[k][j] = 0ULL;

        ulonglong2 p01, p23;
        float2 gpn;
        float4 shn = make_float4(0.f, 0.f, 0.f, 0.f);
        float shn2 = 0.f;
        {
            int e0 = d_csr[beg];
            int s0 = d_srcs[beg];
            const ulonglong2* ap = (const ulonglong2*)&d_Aip[s0 * 4];
            p01 = ap[0]; p23 = ap[1];
            gpn = *(const float2*)&d_g3[e0 * 64 + 2 * lane];
            if (L == 1) shn = *(const float4*)&d_sh[e0 * 8];
            if (L == 2) { shn2 = d_sh[e0 * 8 + 3]; shn = *(const float4*)&d_sh[e0 * 8 + 4]; }
        }
        for (int i = beg; i < end; i++) {
            u64 aa[4] = {p01.x, p01.y, p23.x, p23.y};
            float2 gp = gpn;
            float4 shc = shn;
            float shc2 = shn2;
            if (i + 1 < end) {
                int e2 = d_csr[i + 1];
                int s2 = d_srcs[i + 1];
                const ulonglong2* ap = (const ulonglong2*)&d_Aip[s2 * 4];
                p01 = ap[0]; p23 = ap[1];
                gpn = *(const float2*)&d_g3[e2 * 64 + 2 * lane];
                if (L == 1) shn = *(const float4*)&d_sh[e2 * 8];
                if (L == 2) { shn2 = d_sh[e2 * 8 + 3]; shn = *(const float4*)&d_sh[e2 * 8 + 4]; }
            }

            u64 g00 = pack2(gp.x, gp.x), g11 = pack2(gp.y, gp.y);
            u64 ff[8];
            #pragma unroll
            for (int j = 0; j < 4; j++) { ff[j] = 0ULL; ffma2(ff[j], g00, aa[j]); }
            #pragma unroll
            for (int j = 0; j < 4; j++) { ff[4 + j] = 0ULL; ffma2(ff[4 + j], g11, aa[j]); }

            if (L == 1) {
                float shv[3] = {shc.x, shc.y, shc.z};
                #pragma unroll
                for (int k = 0; k < 3; k++) {
                    u64 ss = pack2(shv[k], shv[k]);
                    #pragma unroll
                    for (int j = 0; j < 8; j++) ffma2(G[k][j], ff[j], ss);
                }
            } else {
                float shv[5] = {shc2, shc.x, shc.y, shc.z, shc.w};
                #pragma unroll
                for (int k = 0; k < 5; k++) {
                    u64 ss = pack2(shv[k], shv[k]);
                    #pragma unroll
                    for (int j = 0; j < 8; j++) ffma2(G[k][j], ff[j], ss);
                }
            }
        }

        float Ad[8];
        {
            const float4* Ai4 = (const float4*)&d_Ai[n * 8];
            float4 b0 = Ai4[0], b1 = Ai4[1];
            Ad[0] = b0.x; Ad[1] = b0.y; Ad[2] = b0.z; Ad[3] = b0.w;
            Ad[4] = b1.x; Ad[5] = b1.y; Ad[6] = b1.z; Ad[7] = b1.w;
        }
        u64 acc[K][2];
        #pragma unroll
        for (int k = 0; k < K; k++) { acc[k][0] = 0ULL; acc[k][1] = 0ULL; }

        #pragma unroll
        for (int j = 0; j < 8; j++) {
            u64 m00, m01, m10, m11;
            {
                int base0 = (lane * 16 + 2 * j) * 32;
                u64 a0 = 0ULL, a1 = 0ULL, b0 = 0ULL, b1 = 0ULL;
                #pragma unroll
                for (int v = 0; v < 8; v++) {
                    u64 ad = pack2(Ad[v], Ad[v]);
                    ulonglong2 mmA =
                        *(const ulonglong2*)&sM[base0 + ((v ^ (lane & 7)) << 2)];
                    ulonglong2 mmB =
                        *(const ulonglong2*)&sM[base0 + 32 + ((v ^ (lane & 7)) << 2)];
                    ffma2(a0, ad, mmA.x);
                    ffma2(a1, ad, mmA.y);
                    ffma2(b0, ad, mmB.x);
                    ffma2(b1, ad, mmB.y);
                }
                m00 = a0; m01 = a1; m10 = b0; m11 = b1;
            }
            #pragma unroll
            for (int k = 0; k < K; k++) {
                float ga, gb; unpack2(G[k][j], ga, gb);
                u64 gaa = pack2(ga, ga), gbb = pack2(gb, gb);
                ffma2(acc[k][0], gaa, m00);
                ffma2(acc[k][1], gaa, m01);
                ffma2(acc[k][0], gbb, m10);
                ffma2(acc[k][1], gbb, m11);
            }
        }

        #pragma unroll
        for (int off = 16; off; off >>= 1) {
            #pragma unroll
            for (int k = 0; k < K; k++) {
                u64 t0 = __shfl_xor_sync(0xffffffffu, acc[k][0], off);
                u64 t1 = __shfl_xor_sync(0xffffffffu, acc[k][1], off);
                ffma2(acc[k][0], t0, ONE2);
                ffma2(acc[k][1], t1, ONE2);
            }
        }

        if (lane == 0) {
            float sc = (1.0f / 64.0f) / (float)deg;
            #pragma unroll
            for (int k = 0; k < K; k++) {
                float W[4];
                unpack2(acc[k][0], W[0], W[1]);
                unpack2(acc[k][1], W[2], W[3]);
                #pragma unroll
                for (int w = 0; w < 4; w++) {
                    if (L == 1) od[w * 3 + k] = W[w] * sc;
                    else        od[w * 5 + k] = W[w] * sc;
                }
            }
        }
    }
}

// ---------------- launch ----------------
extern "C" void kernel_launch(void* const* d_in, const int* in_sizes, int n_in,
                              void* d_out, int out_size) {
    const float* pos      = (const float*)d_in[0];
    const int*   A        = (const int*)d_in[1];
    const int*   batch    = (const int*)d_in[2];
    const int*   edge_src = (const int*)d_in[3];
    const int*   edge_dst = (const int*)d_in[4];
    const float* shifts   = (const float*)d_in[5];
    const float* cell     = (const float*)d_in[6];
    const float* emb      = (const float*)d_in[7];
    const float* fit_w1   = (const float*)d_in[8];
    const float* fit_b1   = (const float*)d_in[9];
    const float* fit_w2   = (const float*)d_in[10];
    const float* fit_b2   = (const float*)d_in[11];
    const float* fit_w3   = (const float*)d_in[12];
    const float* fit_b3   = (const float*)d_in[13];
    const float* fc_w1    = (const float*)d_in[14];
    const float* fc_w2    = (const float*)d_in[15];
    const float* fc_w3    = (const float*)d_in[16];
    const float* fc_w4    = (const float*)d_in[17];
    float* out = (float*)d_out;

    cudaFuncSetAttribute(k_radial, cudaFuncAttributeMaxDynamicSharedMemorySize,
                         R_SMEM_BYTES);
    cudaFuncSetAttribute(k_main0,  cudaFuncAttributeMaxDynamicSharedMemorySize, 65536);
    cudaFuncSetAttribute(k_main<1>, cudaFuncAttributeMaxDynamicSharedMemorySize, 65536);
    cudaFuncSetAttribute(k_main<2>, cudaFuncAttributeMaxDynamicSharedMemorySize, 65536);

    // radial is the 4th launch (ncu capture slot)
    k_zero<<<(N_NODES + 255) / 256, 256>>>();
    k_prepcount<<<NODE_BLOCKS + PERM_BLOCKS + (N_EDGES / 256), 256>>>(
        emb, fit_w1, fit_b1, fit_w2, fit_b2, fit_w3, fit_b3, A, fc_w4, edge_dst);
    k_scan1<<<SCAN_BLOCKS, 256>>>();
    k_radial<<<N_EDGES / 128, 512, R_SMEM_BYTES>>>(pos, batch, shifts, cell,
                                                   edge_src, edge_dst,
                                                   fc_w1, fc_w2, fc_w3);
    k_scan2<<<1, 128>>>();
    k_scan3<<<SCAN_BLOCKS, 256>>>();
    k_scatter<<<N_EDGES / 256, 256>>>(edge_dst, edge_src);
    k_main0<<<296, 256, 65536>>>(out);
    k_main<1><<<296, 256, 65536>>>(out);
    k_main<2><<<296, 256, 65536>>>(out);
}